// round 12
// baseline (speedup 1.0000x reference)
#include <cuda_runtime.h>
#include <cuda_bf16.h>
#include <math.h>

#define BB 8
#define LL 1000
#define DD 512
#define HH 8
#define DKK 64
#define NTOK (BB*LL)
#define RELN (2*LL-1)

typedef unsigned int u32;

// ------------------------------------------------------------ scratch (bf16 hi/lo planes)
__device__ __nv_bfloat16 g_xnh[NTOK*DD];
__device__ __nv_bfloat16 g_xnl[NTOK*DD];
__device__ __nv_bfloat16 g_qh[NTOK*DD];  // (B,H,L,dk)
__device__ __nv_bfloat16 g_ql[NTOK*DD];
__device__ __nv_bfloat16 g_kh[NTOK*DD];  // pre-scaled by 1/8
__device__ __nv_bfloat16 g_kl[NTOK*DD];
__device__ __nv_bfloat16 g_vh[NTOK*DD];
__device__ __nv_bfloat16 g_vl[NTOK*DD];
__device__ __nv_bfloat16 g_cth[NTOK*DD]; // ctx (B,L,D)
__device__ __nv_bfloat16 g_ctl[NTOK*DD];
__device__ __nv_bfloat16 g_wh[4*DD*DD];  // [Wq;Wk;Wv;Wo] hi
__device__ __nv_bfloat16 g_wl[4*DD*DD];
__device__ __nv_bfloat16 g_relh[RELN*DKK];
__device__ __nv_bfloat16 g_rell[RELN*DKK];

// ------------------------------------------------------------ asm helpers
__device__ __forceinline__ void mma16816(float* d, const u32* a, const u32* b) {
    asm volatile(
        "mma.sync.aligned.m16n8k16.row.col.f32.bf16.bf16.f32 "
        "{%0,%1,%2,%3}, {%4,%5,%6,%7}, {%8,%9}, {%0,%1,%2,%3};"
        : "+f"(d[0]), "+f"(d[1]), "+f"(d[2]), "+f"(d[3])
        : "r"(a[0]), "r"(a[1]), "r"(a[2]), "r"(a[3]), "r"(b[0]), "r"(b[1]));
}
__device__ __forceinline__ void ldsm4(u32* r, u32 addr) {
    asm volatile("ldmatrix.sync.aligned.m8n8.x4.shared.b16 {%0,%1,%2,%3}, [%4];"
                 : "=r"(r[0]), "=r"(r[1]), "=r"(r[2]), "=r"(r[3]) : "r"(addr));
}
__device__ __forceinline__ void ldsm4t(u32* r, u32 addr) {
    asm volatile("ldmatrix.sync.aligned.m8n8.x4.trans.shared.b16 {%0,%1,%2,%3}, [%4];"
                 : "=r"(r[0]), "=r"(r[1]), "=r"(r[2]), "=r"(r[3]) : "r"(addr));
}
__device__ __forceinline__ void cpa16(u32 dst, const void* src, int sz) {
    asm volatile("cp.async.cg.shared.global [%0], [%1], 16, %2;"
                 :: "r"(dst), "l"(src), "r"(sz));
}
__device__ __forceinline__ void cp_commit() {
    asm volatile("cp.async.commit_group;");
}
template <int N> __device__ __forceinline__ void cp_wait() {
    asm volatile("cp.async.wait_group %0;" :: "n"(N));
}
__device__ __forceinline__ void split_store2(__nv_bfloat16* H, __nv_bfloat16* L,
                                             size_t idx, float x, float y) {
    __nv_bfloat16 hx = __float2bfloat16_rn(x), hy = __float2bfloat16_rn(y);
    *reinterpret_cast<__nv_bfloat162*>(&H[idx]) = __halves2bfloat162(hx, hy);
    *reinterpret_cast<__nv_bfloat162*>(&L[idx]) = __halves2bfloat162(
        __float2bfloat16_rn(x - __bfloat162float(hx)),
        __float2bfloat16_rn(y - __bfloat162float(hy)));
}
__device__ __forceinline__ void pack_hl(float x, float y, u32& h, u32& l) {
    __nv_bfloat16 hx = __float2bfloat16_rn(x), hy = __float2bfloat16_rn(y);
    __nv_bfloat162 hv = __halves2bfloat162(hx, hy);
    __nv_bfloat162 lv = __halves2bfloat162(
        __float2bfloat16_rn(x - __bfloat162float(hx)),
        __float2bfloat16_rn(y - __bfloat162float(hy)));
    h = *reinterpret_cast<u32*>(&hv);
    l = *reinterpret_cast<u32*>(&lv);
}

// ------------------------------------------------------------ LayerNorm + bf16 split
__global__ __launch_bounds__(128) void ln_kernel(const float* __restrict__ x,
                                                 const float* __restrict__ gamma,
                                                 const float* __restrict__ beta)
{
    int tok = blockIdx.x;
    int tid = threadIdx.x;
    const float4 v = reinterpret_cast<const float4*>(x + (size_t)tok * DD)[tid];
    float s  = v.x + v.y + v.z + v.w;
    float ss = v.x*v.x + v.y*v.y + v.z*v.z + v.w*v.w;
#pragma unroll
    for (int o = 16; o; o >>= 1) {
        s  += __shfl_xor_sync(0xffffffffu, s,  o);
        ss += __shfl_xor_sync(0xffffffffu, ss, o);
    }
    __shared__ float sh[8];
    int w = tid >> 5, lane = tid & 31;
    if (lane == 0) { sh[w] = s; sh[4 + w] = ss; }
    __syncthreads();
    s  = sh[0] + sh[1] + sh[2] + sh[3];
    ss = sh[4] + sh[5] + sh[6] + sh[7];
    float mu  = s * (1.0f / DD);
    float var = ss * (1.0f / DD) - mu * mu;
    float inv = rsqrtf(var + 1e-5f);
    float4 g = reinterpret_cast<const float4*>(gamma)[tid];
    float4 b = reinterpret_cast<const float4*>(beta)[tid];
    float o0 = (v.x - mu) * inv * g.x + b.x;
    float o1 = (v.y - mu) * inv * g.y + b.y;
    float o2 = (v.z - mu) * inv * g.z + b.z;
    float o3 = (v.w - mu) * inv * g.w + b.w;
    size_t base = (size_t)tok * DD + tid * 4;
    split_store2(g_xnh, g_xnl, base,     o0, o1);
    split_store2(g_xnh, g_xnl, base + 2, o2, o3);
}

// ------------------------------------------------------------ fused weight/rel split
__global__ __launch_bounds__(256) void split_all(const float* __restrict__ Wq,
                                                 const float* __restrict__ Wk,
                                                 const float* __restrict__ Wv,
                                                 const float* __restrict__ Wo,
                                                 const float* __restrict__ rel)
{
    int bid = blockIdx.x;
    if (bid < 1024) {
        int w = bid >> 8;
        const float* src = (w == 0) ? Wq : (w == 1) ? Wk : (w == 2) ? Wv : Wo;
        size_t i = ((size_t)(bid & 255) * 256 + threadIdx.x) * 4;
        float4 v = *reinterpret_cast<const float4*>(src + i);
        size_t o = (size_t)w * DD * DD + i;
        split_store2(g_wh, g_wl, o,     v.x, v.y);
        split_store2(g_wh, g_wl, o + 2, v.z, v.w);
    } else {
        int iv = (bid - 1024) * 256 + threadIdx.x;
        if (iv < RELN * DKK / 4) {
            size_t i = (size_t)iv * 4;
            float4 v = *reinterpret_cast<const float4*>(rel + i);
            split_store2(g_relh, g_rell, i,     v.x, v.y);
            split_store2(g_relh, g_rell, i + 2, v.z, v.w);
        }
    }
}

// ------------------------------------------------------------ pipelined fused GEMM (R5)
#define GS 40
#define PLG (128 * GS)
#define AH_OFF 0
#define AL_OFF (PLG * 2)
#define BH_OFF (PLG * 4)
#define BL_OFF (PLG * 6)
#define STAGE_B (PLG * 8)
#define GEMM_SMEM (2 * STAGE_B)

__global__ __launch_bounds__(256, 2) void gemm_tc_kernel(
    const __nv_bfloat16* __restrict__ Ah, const __nv_bfloat16* __restrict__ Al,
    const __nv_bfloat16* __restrict__ Wh, const __nv_bfloat16* __restrict__ Wl,
    const float* __restrict__ b0, const float* __restrict__ b1,
    const float* __restrict__ b2,
    float* __restrict__ CoutF, const float* __restrict__ res,
    __nv_bfloat16* __restrict__ Qh, __nv_bfloat16* __restrict__ Ql,
    __nv_bfloat16* __restrict__ Kh, __nv_bfloat16* __restrict__ Kl,
    __nv_bfloat16* __restrict__ Vh, __nv_bfloat16* __restrict__ Vl,
    int mode)
{
    extern __shared__ __align__(16) char smem[];
    const u32 sb = (u32)__cvta_generic_to_shared(smem);

    const int tid = threadIdx.x;
    const int lane = tid & 31, wid = tid >> 5;
    const int wm = wid & 1, wn = wid >> 1;
    const int m0 = blockIdx.y * 128;
    const int n0 = blockIdx.x * 128;

    const int lr = tid >> 2;
    const int lc = (tid & 3) << 3;

    float acc[4][4][4] = {};

    auto load_stage = [&](int k0, int s) {
        u32 base = sb + s * STAGE_B;
#pragma unroll
        for (int it = 0; it < 2; it++) {
            int r = lr + it * 64;
            u32 soff = (u32)(r * GS + lc) * 2;
            int mg = m0 + r;
            int mclamp = mg < NTOK ? mg : NTOK - 1;
            int sz = mg < NTOK ? 16 : 0;
            cpa16(base + AH_OFF + soff, &Ah[(size_t)mclamp * DD + k0 + lc], sz);
            cpa16(base + AL_OFF + soff, &Al[(size_t)mclamp * DD + k0 + lc], sz);
            int ng = n0 + r;
            cpa16(base + BH_OFF + soff, &Wh[(size_t)ng * DD + k0 + lc], 16);
            cpa16(base + BL_OFF + soff, &Wl[(size_t)ng * DD + k0 + lc], 16);
        }
        cp_commit();
    };

    load_stage(0, 0);

#pragma unroll 1
    for (int ks = 0; ks < 16; ks++) {
        if (ks + 1 < 16) load_stage((ks + 1) * 32, (ks + 1) & 1);
        if (ks + 1 < 16) cp_wait<1>(); else cp_wait<0>();
        __syncthreads();

        u32 base = sb + (ks & 1) * STAGE_B;
#pragma unroll
        for (int kt = 0; kt < 32; kt += 16) {
            u32 bfh[8], bfl[8];
            {
                int g = lane >> 3, r8 = lane & 7;
                int brow = wn * 32 + ((g >> 1) & 1) * 8 + r8;
                int bcol = kt + (g & 1) * 8;
                u32 boff = base + (u32)(brow * GS + bcol) * 2;
                ldsm4(&bfh[0], boff + BH_OFF);
                ldsm4(&bfh[4], boff + BH_OFF + 16 * GS * 2);
                ldsm4(&bfl[0], boff + BL_OFF);
                ldsm4(&bfl[4], boff + BL_OFF + 16 * GS * 2);
            }
#pragma unroll
            for (int mt = 0; mt < 4; mt++) {
                u32 afh[4], afl[4];
                int arow = wm * 64 + mt * 16 + (lane & 15);
                int acol = kt + ((lane >> 4) << 3);
                u32 aoff = base + (u32)(arow * GS + acol) * 2;
                ldsm4(afh, aoff + AH_OFF);
                ldsm4(afl, aoff + AL_OFF);
#pragma unroll
                for (int nt = 0; nt < 4; nt++) {
                    mma16816(acc[mt][nt], afh, &bfh[nt * 2]);
                    mma16816(acc[mt][nt], afh, &bfl[nt * 2]);
                    mma16816(acc[mt][nt], afl, &bfh[nt * 2]);
                }
            }
        }
        __syncthreads();
    }

    const int r = lane >> 2, c = (lane & 3) << 1;
    if (mode == 0) {
        int wsel = n0 >> 9;
        const float* bias = wsel == 0 ? b0 : (wsel == 1 ? b1 : b2);
        float scl = wsel == 1 ? 0.125f : 1.0f;
        __nv_bfloat16* OH = wsel == 0 ? Qh : (wsel == 1 ? Kh : Vh);
        __nv_bfloat16* OL = wsel == 0 ? Ql : (wsel == 1 ? Kl : Vl);
        int nl0 = (n0 & 511) + wn * 32;
#pragma unroll
        for (int mt = 0; mt < 4; mt++) {
#pragma unroll
            for (int nt = 0; nt < 4; nt++) {
                int nl = nl0 + nt * 8 + c;
                float bb0 = bias[nl], bb1 = bias[nl + 1];
                int h = nl >> 6, dd = nl & 63;
#pragma unroll
                for (int half = 0; half < 2; half++) {
                    int m = m0 + wm * 64 + mt * 16 + r + half * 8;
                    if (m >= NTOK) continue;
                    int bidx = m / LL, l = m - bidx * LL;
                    float ox = (acc[mt][nt][half * 2]     + bb0) * scl;
                    float oy = (acc[mt][nt][half * 2 + 1] + bb1) * scl;
                    size_t idx = ((size_t)(bidx * HH + h) * LL + l) * DKK + dd;
                    split_store2(OH, OL, idx, ox, oy);
                }
            }
        }
    } else {
#pragma unroll
        for (int mt = 0; mt < 4; mt++) {
#pragma unroll
            for (int nt = 0; nt < 4; nt++) {
                int n = n0 + wn * 32 + nt * 8 + c;
                float bb0 = b0[n], bb1 = b0[n + 1];
#pragma unroll
                for (int half = 0; half < 2; half++) {
                    int m = m0 + wm * 64 + mt * 16 + r + half * 8;
                    if (m >= NTOK) continue;
                    size_t off = (size_t)m * DD + n;
                    float2 r2 = *reinterpret_cast<const float2*>(&res[off]);
                    *reinterpret_cast<float2*>(&CoutF[off]) =
                        make_float2(acc[mt][nt][half * 2] + bb0 + r2.x,
                                    acc[mt][nt][half * 2 + 1] + bb1 + r2.y);
                }
            }
        }
    }
}

// --------------------------------------------------------- flash attention: pipelined R-regs
// warps 0-3 (q): S -> softmax -> PV (full 3-term).
// warps 4-7 (rel): hold band t+1 in regs; flush to ring in phase 1 (|| q's S);
//                  compute band t+2 in phase 2 (|| q's softmax+PV).
// 2 barriers per tile; V load + K prefetch off the critical path.
#define SSTR 72
#define RSTR 132

#define AQH   0
#define AQL   9216
#define AKH   18432
#define AKL   27648
#define AVH   36864
#define AVL   46080
#define ARNH  55296
#define ARNL  64512
#define ARING 73728
#define ATTN_SMEM 107520

__global__ __launch_bounds__(256, 2) void attn_tc_kernel(
    const __nv_bfloat16* __restrict__ relh, const __nv_bfloat16* __restrict__ rell)
{
    extern __shared__ __align__(16) char smem[];
    __nv_bfloat16* sQh = (__nv_bfloat16*)(smem + AQH);
    __nv_bfloat16* sQl = (__nv_bfloat16*)(smem + AQL);
    float* sRing = (float*)(smem + ARING);

    const int tid = threadIdx.x;
    const int lane = tid & 31, wid = tid >> 5;
    const bool isq = wid < 4;
    const int wq = wid & 3;
    const int bh = blockIdx.y;
    const int i0 = blockIdx.x << 6;
    const u32 sb = (u32)__cvta_generic_to_shared(smem);
    const int g = lane >> 3, r8 = lane & 7;
    const int r4 = lane >> 2, c2 = (lane & 3) << 1;
    const int row0 = (wq << 4) + r4;

    const __nv_bfloat16* qh = g_qh + (size_t)bh * LL * DKK;
    const __nv_bfloat16* ql = g_ql + (size_t)bh * LL * DKK;
    const __nv_bfloat16* kh = g_kh + (size_t)bh * LL * DKK;
    const __nv_bfloat16* kl = g_kl + (size_t)bh * LL * DKK;
    const __nv_bfloat16* vh = g_vh + (size_t)bh * LL * DKK;
    const __nv_bfloat16* vl = g_vl + (size_t)bh * LL * DKK;

    // cp.async tile loaders (16B chunks, zero-fill out of range)
    auto cpa_k = [&](int j0) {
#pragma unroll
        for (int it = 0; it < 2; it++) {
            int idx = tid + (it << 8);
            int r = idx >> 3, c = (idx & 7) << 3;
            int jg = j0 + r;
            int jc = jg < LL ? jg : 0;
            int sz = jg < LL ? 16 : 0;
            u32 off = (u32)(r * SSTR + c) * 2;
            cpa16(sb + AKH + off, &kh[(size_t)jc * DKK + c], sz);
            cpa16(sb + AKL + off, &kl[(size_t)jc * DKK + c], sz);
        }
    };
    auto cpa_v = [&](int j0) {
#pragma unroll
        for (int it = 0; it < 2; it++) {
            int idx = tid + (it << 8);
            int r = idx >> 3, c = (idx & 7) << 3;
            int jg = j0 + r;
            int jc = jg < LL ? jg : 0;
            int sz = jg < LL ? 16 : 0;
            u32 off = (u32)(r * SSTR + c) * 2;
            cpa16(sb + AVH + off, &vh[(size_t)jc * DKK + c], sz);
            cpa16(sb + AVL + off, &vl[(size_t)jc * DKK + c], sz);
        }
    };
    auto cpa_rel = [&](int mstart) {
#pragma unroll
        for (int it = 0; it < 2; it++) {
            int idx = tid + (it << 8);
            int r = idx >> 3, c = (idx & 7) << 3;
            int mg = mstart + r;
            bool ok = (mg >= 0 && mg < RELN);
            int mc = ok ? mg : 0;
            int sz = ok ? 16 : 0;
            u32 off = (u32)(r * SSTR + c) * 2;
            cpa16(sb + ARNH + off, &relh[(size_t)mc * DKK + c], sz);
            cpa16(sb + ARNL + off, &rell[(size_t)mc * DKK + c], sz);
        }
    };

    float big[16][4] = {};
    float mrow[2] = {-1e30f, -1e30f};
    float lrow[2] = {0.f, 0.f};

    auto gemm64 = [&](u32 bhof, u32 blof) {
#pragma unroll
        for (int q = 0; q < 8; q++)
            big[q][0] = big[q][1] = big[q][2] = big[q][3] = 0.f;
#pragma unroll
        for (int kc = 0; kc < 4; kc++) {
            u32 afh[4], afl[4];
            int arow = (wq << 4) + (lane & 15);
            int acol = (kc << 4) + ((lane >> 4) << 3);
            u32 aoff = (u32)(arow * SSTR + acol) * 2;
            ldsm4(afh, sb + AQH + aoff);
            ldsm4(afl, sb + AQL + aoff);
            int bcol = (kc << 4) + ((g & 1) << 3);
#pragma unroll
            for (int cb = 0; cb < 2; cb++) {
                u32 bh_[8], bl_[8];
                int brow = cb * 32 + ((g >> 1) & 1) * 8 + r8;
                u32 boff = (u32)(brow * SSTR + bcol) * 2;
                ldsm4(&bh_[0], sb + bhof + boff);
                ldsm4(&bh_[4], sb + bhof + boff + 16 * SSTR * 2);
                ldsm4(&bl_[0], sb + blof + boff);
                ldsm4(&bl_[4], sb + blof + boff + 16 * SSTR * 2);
#pragma unroll
                for (int nt2 = 0; nt2 < 4; nt2++) {
                    mma16816(big[cb * 4 + nt2], afh, &bh_[nt2 * 2]);
                    mma16816(big[cb * 4 + nt2], afh, &bl_[nt2 * 2]);
                    mma16816(big[cb * 4 + nt2], afl, &bh_[nt2 * 2]);
                }
            }
        }
    };
    auto ring_write = [&](int base_w) {
#pragma unroll
        for (int q = 0; q < 8; q++) {
            int col = base_w + (q << 3) + c2;
            *reinterpret_cast<float2*>(&sRing[row0 * RSTR + col]) =
                make_float2(big[q][0], big[q][1]);
            *reinterpret_cast<float2*>(&sRing[(row0 + 8) * RSTR + col]) =
                make_float2(big[q][2], big[q][3]);
        }
    };

    // ---- prologue ----
    // band b rel rows start at: 936 - i0 + 64*b   (band b = offsets [64b, 64b+63])
    cpa_rel(936 - i0);               // band 0
    cp_commit();
    // Q tile (regular loads, overlap with cp.async)
#pragma unroll
    for (int it = 0; it < 2; it++) {
        int idx = tid + it * 256;
        int r = idx >> 3, c = (idx & 7) << 3;
        int rg = i0 + r;
        uint4 h4 = make_uint4(0,0,0,0), l4 = make_uint4(0,0,0,0);
        if (rg < LL) {
            h4 = *reinterpret_cast<const uint4*>(&qh[(size_t)rg * DKK + c]);
            l4 = *reinterpret_cast<const uint4*>(&ql[(size_t)rg * DKK + c]);
        }
        *reinterpret_cast<uint4*>(&sQh[r * SSTR + c]) = h4;
        *reinterpret_cast<uint4*>(&sQl[r * SSTR + c]) = l4;
    }
    cp_wait<0>();
    __syncthreads();
    if (!isq) {                      // band 0 -> ring slots [0..63]
        gemm64(ARNH, ARNL);
        ring_write(0);
    }
    __syncthreads();                 // rel_new consumed
    cpa_rel(936 - i0 + 64);          // band 1
    cpa_k(0);                        // K(0)
    cp_commit();
    cp_wait<0>();
    __syncthreads();
    if (!isq) gemm64(ARNH, ARNL);    // band 1 -> regs (held across tiles)

#pragma unroll 1
    for (int t = 0; t < 16; t++) {
        const int j0 = t << 6;
        cp_wait<0>();                // K(t) arrived (prefetched last phase 2)
        __syncthreads();             // syncA: prev tile fully done; V/rel_new free
        cpa_v(j0);
        cpa_rel(936 - i0 + 64 * (t + 2));   // rows for band t+2
        cp_commit();

        // -------- phase 1: q: S(t) | rel: flush band t+1 to ring --------
        if (isq) {
            gemm64(AKH, AKL);
        } else {
            ring_write((64 * (t + 1)) & 127);
        }
        cp_wait<0>();                // V(t) + rel_new(band t+2)
        __syncthreads();             // syncB: ring(t) complete; K consumed
        if (t + 1 < 16) {            // prefetch K(t+1) through phase 2
            cpa_k((t + 1) << 6);
            cp_commit();
        }

        // -------- phase 2: q: softmax + PV | rel: band t+2 -> regs --------
        if (isq) {
            const int bt = (t << 6) & 127;
            float mx0 = -1e30f, mx1 = -1e30f;
#pragma unroll
            for (int nt = 0; nt < 8; nt++) {
#pragma unroll
                for (int k = 0; k < 2; k++) {
                    int c = (nt << 3) + c2 + k;
                    int s0 = (bt + c - row0 + 63) & 127;
                    int s1 = (bt + c - row0 - 8 + 63) & 127;
                    float v0 = big[nt][k]     + sRing[row0 * RSTR + s0];
                    float v1 = big[nt][2 + k] + sRing[(row0 + 8) * RSTR + s1];
                    bool valid = (j0 + c) < LL;
                    v0 = valid ? v0 : -1e30f;
                    v1 = valid ? v1 : -1e30f;
                    big[nt][k] = v0; big[nt][2 + k] = v1;
                    mx0 = fmaxf(mx0, v0);
                    mx1 = fmaxf(mx1, v1);
                }
            }
            mx0 = fmaxf(mx0, __shfl_xor_sync(0xffffffffu, mx0, 1));
            mx0 = fmaxf(mx0, __shfl_xor_sync(0xffffffffu, mx0, 2));
            mx1 = fmaxf(mx1, __shfl_xor_sync(0xffffffffu, mx1, 1));
            mx1 = fmaxf(mx1, __shfl_xor_sync(0xffffffffu, mx1, 2));
            float m0n = fmaxf(mrow[0], mx0);
            float m1n = fmaxf(mrow[1], mx1);
            float corr0 = __expf(mrow[0] - m0n);
            float corr1 = __expf(mrow[1] - m1n);
            mrow[0] = m0n; mrow[1] = m1n;
            float s0 = 0.f, s1 = 0.f;
#pragma unroll
            for (int nt = 0; nt < 8; nt++) {
                float p0 = __expf(big[nt][0] - m0n);
                float p1 = __expf(big[nt][1] - m0n);
                float p2 = __expf(big[nt][2] - m1n);
                float p3 = __expf(big[nt][3] - m1n);
                big[nt][0] = p0; big[nt][1] = p1; big[nt][2] = p2; big[nt][3] = p3;
                s0 += p0 + p1; s1 += p2 + p3;
                big[8 + nt][0] *= corr0; big[8 + nt][1] *= corr0;
                big[8 + nt][2] *= corr1; big[8 + nt][3] *= corr1;
            }
            s0 += __shfl_xor_sync(0xffffffffu, s0, 1);
            s0 += __shfl_xor_sync(0xffffffffu, s0, 2);
            s1 += __shfl_xor_sync(0xffffffffu, s1, 1);
            s1 += __shfl_xor_sync(0xffffffffu, s1, 2);
            lrow[0] = lrow[0] * corr0 + s0;
            lrow[1] = lrow[1] * corr1 + s1;

            // PV with register P (C-frag == A-frag layout), full 3-term
#pragma unroll
            for (int kc = 0; kc < 4; kc++) {
                u32 pfh[4], pfl[4];
                pack_hl(big[2*kc][0],   big[2*kc][1],   pfh[0], pfl[0]);
                pack_hl(big[2*kc][2],   big[2*kc][3],   pfh[1], pfl[1]);
                pack_hl(big[2*kc+1][0], big[2*kc+1][1], pfh[2], pfl[2]);
                pack_hl(big[2*kc+1][2], big[2*kc+1][3], pfh[3], pfl[3]);
#pragma unroll
                for (int vcb = 0; vcb < 2; vcb++) {
                    u32 vh_[8], vl_[8];
                    int vrow = (kc << 4) + ((g & 1) << 3) + r8;
                    int vcol = (vcb << 5) + (((g >> 1) & 1) << 3);
                    u32 voff = (u32)(vrow * SSTR + vcol) * 2;
                    ldsm4t(&vh_[0], sb + AVH + voff);
                    ldsm4t(&vh_[4], sb + AVH + voff + 32);
                    ldsm4t(&vl_[0], sb + AVL + voff);
                    ldsm4t(&vl_[4], sb + AVL + voff + 32);
#pragma unroll
                    for (int nt2 = 0; nt2 < 4; nt2++) {
                        float* oa = big[8 + vcb * 4 + nt2];
                        mma16816(oa, pfh, &vh_[nt2 * 2]);
                        mma16816(oa, pfh, &vl_[nt2 * 2]);
                        mma16816(oa, pfl, &vh_[nt2 * 2]);
                    }
                }
            }
        } else {
            gemm64(ARNH, ARNL);      // band t+2 -> regs (flushed next tile)
        }
    }

    // epilogue (qwarps): normalize + split-store ctx
    if (isq) {
        int b = bh >> 3, h = bh & 7;
        float li0 = 1.0f / lrow[0];
        float li1 = 1.0f / lrow[1];
        int rg0 = i0 + row0, rg1 = rg0 + 8;
#pragma unroll
        for (int nt = 0; nt < 8; nt++) {
            int col = h * 64 + (nt << 3) + c2;
            if (rg0 < LL)
                split_store2(g_cth, g_ctl, ((size_t)(b * LL + rg0)) * DD + col,
                             big[8 + nt][0] * li0, big[8 + nt][1] * li0);
            if (rg1 < LL)
                split_store2(g_cth, g_ctl, ((size_t)(b * LL + rg1)) * DD + col,
                             big[8 + nt][2] * li1, big[8 + nt][3] * li1);
        }
    }
}

// ---------------------------------------------------------------- launcher
extern "C" void kernel_launch(void* const* d_in, const int* in_sizes, int n_in,
                              void* d_out, int out_size)
{
    const float* x     = (const float*)d_in[0];
    const float* Wq    = (const float*)d_in[1];
    const float* bq    = (const float*)d_in[2];
    const float* Wk    = (const float*)d_in[3];
    const float* bk    = (const float*)d_in[4];
    const float* Wv    = (const float*)d_in[5];
    const float* bv    = (const float*)d_in[6];
    const float* Wo    = (const float*)d_in[7];
    const float* bo    = (const float*)d_in[8];
    const float* rel   = (const float*)d_in[9];
    const float* gamma = (const float*)d_in[10];
    const float* beta  = (const float*)d_in[11];
    float* out = (float*)d_out;

    __nv_bfloat16 *xnh, *xnl, *qh, *ql, *kh, *kl, *vh, *vl, *cth, *ctl, *wh, *wl, *relh, *rell;
    cudaGetSymbolAddress((void**)&xnh, g_xnh);
    cudaGetSymbolAddress((void**)&xnl, g_xnl);
    cudaGetSymbolAddress((void**)&qh,  g_qh);
    cudaGetSymbolAddress((void**)&ql,  g_ql);
    cudaGetSymbolAddress((void**)&kh,  g_kh);
    cudaGetSymbolAddress((void**)&kl,  g_kl);
    cudaGetSymbolAddress((void**)&vh,  g_vh);
    cudaGetSymbolAddress((void**)&vl,  g_vl);
    cudaGetSymbolAddress((void**)&cth, g_cth);
    cudaGetSymbolAddress((void**)&ctl, g_ctl);
    cudaGetSymbolAddress((void**)&wh,  g_wh);
    cudaGetSymbolAddress((void**)&wl,  g_wl);
    cudaGetSymbolAddress((void**)&relh, g_relh);
    cudaGetSymbolAddress((void**)&rell, g_rell);

    cudaFuncSetAttribute(attn_tc_kernel, cudaFuncAttributeMaxDynamicSharedMemorySize,
                         ATTN_SMEM);
    cudaFuncSetAttribute(gemm_tc_kernel, cudaFuncAttributeMaxDynamicSharedMemorySize,
                         GEMM_SMEM);

    // ln (s0) || weight/rel split (s2), then join — capture-safe (proven R9/R10)
    cudaStream_t s2;
    cudaStreamCreateWithFlags(&s2, cudaStreamNonBlocking);
    cudaEvent_t eFork, eWs;
    cudaEventCreateWithFlags(&eFork, cudaEventDisableTiming);
    cudaEventCreateWithFlags(&eWs,   cudaEventDisableTiming);
    cudaEventRecord(eFork, 0);
    cudaStreamWaitEvent(s2, eFork, 0);
    ln_kernel<<<NTOK, 128>>>(x, gamma, beta);
    split_all<<<1149, 256, 0, s2>>>(Wq, Wk, Wv, Wo, rel);
    cudaEventRecord(eWs, s2);
    cudaStreamWaitEvent(0, eWs, 0);

    // fused QKV
    dim3 gq(1536 / 128, (NTOK + 127) / 128);  // (12, 63)
    gemm_tc_kernel<<<gq, 256, GEMM_SMEM>>>(xnh, xnl, wh, wl, bq, bk, bv,
                                           nullptr, nullptr,
                                           qh, ql, kh, kl, vh, vl, 0);

    dim3 ga((LL + 63) / 64, BB * HH);  // (16, 64)
    attn_tc_kernel<<<ga, 256, ATTN_SMEM>>>(relh, rell);

    dim3 go(DD / 128, (NTOK + 127) / 128);    // (4, 63)
    gemm_tc_kernel<<<go, 256, GEMM_SMEM>>>(cth, ctl, wh + 3*DD*DD, wl + 3*DD*DD,
                                           bo, nullptr, nullptr,
                                           out, x,
                                           nullptr, nullptr, nullptr, nullptr,
                                           nullptr, nullptr, 1);
}

// round 13
// speedup vs baseline: 1.0507x; 1.0507x over previous
#include <cuda_runtime.h>
#include <cuda_bf16.h>
#include <math.h>

#define BB 8
#define LL 1000
#define DD 512
#define HH 8
#define DKK 64
#define NTOK (BB*LL)
#define RELN (2*LL-1)

typedef unsigned int u32;

// ------------------------------------------------------------ scratch (bf16 hi/lo planes)
__device__ __nv_bfloat16 g_xnh[NTOK*DD];
__device__ __nv_bfloat16 g_xnl[NTOK*DD];
__device__ __nv_bfloat16 g_qh[NTOK*DD];  // (B,H,L,dk)
__device__ __nv_bfloat16 g_ql[NTOK*DD];
__device__ __nv_bfloat16 g_kh[NTOK*DD];  // pre-scaled by 1/8
__device__ __nv_bfloat16 g_kl[NTOK*DD];
__device__ __nv_bfloat16 g_vh[NTOK*DD];
__device__ __nv_bfloat16 g_vl[NTOK*DD];
__device__ __nv_bfloat16 g_cth[NTOK*DD]; // ctx (B,L,D)
__device__ __nv_bfloat16 g_ctl[NTOK*DD];
__device__ __nv_bfloat16 g_wh[4*DD*DD];  // [Wq;Wk;Wv;Wo] hi
__device__ __nv_bfloat16 g_wl[4*DD*DD];
__device__ __nv_bfloat16 g_relh[RELN*DKK];
__device__ __nv_bfloat16 g_rell[RELN*DKK];

// ------------------------------------------------------------ asm helpers
__device__ __forceinline__ void mma16816(float* d, const u32* a, const u32* b) {
    asm volatile(
        "mma.sync.aligned.m16n8k16.row.col.f32.bf16.bf16.f32 "
        "{%0,%1,%2,%3}, {%4,%5,%6,%7}, {%8,%9}, {%0,%1,%2,%3};"
        : "+f"(d[0]), "+f"(d[1]), "+f"(d[2]), "+f"(d[3])
        : "r"(a[0]), "r"(a[1]), "r"(a[2]), "r"(a[3]), "r"(b[0]), "r"(b[1]));
}
__device__ __forceinline__ void ldsm4(u32* r, u32 addr) {
    asm volatile("ldmatrix.sync.aligned.m8n8.x4.shared.b16 {%0,%1,%2,%3}, [%4];"
                 : "=r"(r[0]), "=r"(r[1]), "=r"(r[2]), "=r"(r[3]) : "r"(addr));
}
__device__ __forceinline__ void ldsm4t(u32* r, u32 addr) {
    asm volatile("ldmatrix.sync.aligned.m8n8.x4.trans.shared.b16 {%0,%1,%2,%3}, [%4];"
                 : "=r"(r[0]), "=r"(r[1]), "=r"(r[2]), "=r"(r[3]) : "r"(addr));
}
__device__ __forceinline__ void cpa16(u32 dst, const void* src, int sz) {
    asm volatile("cp.async.cg.shared.global [%0], [%1], 16, %2;"
                 :: "r"(dst), "l"(src), "r"(sz));
}
__device__ __forceinline__ void cp_commit() {
    asm volatile("cp.async.commit_group;");
}
template <int N> __device__ __forceinline__ void cp_wait() {
    asm volatile("cp.async.wait_group %0;" :: "n"(N));
}
__device__ __forceinline__ void split_store2(__nv_bfloat16* H, __nv_bfloat16* L,
                                             size_t idx, float x, float y) {
    __nv_bfloat16 hx = __float2bfloat16_rn(x), hy = __float2bfloat16_rn(y);
    *reinterpret_cast<__nv_bfloat162*>(&H[idx]) = __halves2bfloat162(hx, hy);
    *reinterpret_cast<__nv_bfloat162*>(&L[idx]) = __halves2bfloat162(
        __float2bfloat16_rn(x - __bfloat162float(hx)),
        __float2bfloat16_rn(y - __bfloat162float(hy)));
}
__device__ __forceinline__ u32 pack_h(float x, float y) {
    __nv_bfloat162 hv = __halves2bfloat162(__float2bfloat16_rn(x),
                                           __float2bfloat16_rn(y));
    return *reinterpret_cast<u32*>(&hv);
}

// ------------------------------------------------------------ LayerNorm + bf16 split
__global__ __launch_bounds__(128) void ln_kernel(const float* __restrict__ x,
                                                 const float* __restrict__ gamma,
                                                 const float* __restrict__ beta)
{
    int tok = blockIdx.x;
    int tid = threadIdx.x;
    const float4 v = reinterpret_cast<const float4*>(x + (size_t)tok * DD)[tid];
    float s  = v.x + v.y + v.z + v.w;
    float ss = v.x*v.x + v.y*v.y + v.z*v.z + v.w*v.w;
#pragma unroll
    for (int o = 16; o; o >>= 1) {
        s  += __shfl_xor_sync(0xffffffffu, s,  o);
        ss += __shfl_xor_sync(0xffffffffu, ss, o);
    }
    __shared__ float sh[8];
    int w = tid >> 5, lane = tid & 31;
    if (lane == 0) { sh[w] = s; sh[4 + w] = ss; }
    __syncthreads();
    s  = sh[0] + sh[1] + sh[2] + sh[3];
    ss = sh[4] + sh[5] + sh[6] + sh[7];
    float mu  = s * (1.0f / DD);
    float var = ss * (1.0f / DD) - mu * mu;
    float inv = rsqrtf(var + 1e-5f);
    float4 g = reinterpret_cast<const float4*>(gamma)[tid];
    float4 b = reinterpret_cast<const float4*>(beta)[tid];
    float o0 = (v.x - mu) * inv * g.x + b.x;
    float o1 = (v.y - mu) * inv * g.y + b.y;
    float o2 = (v.z - mu) * inv * g.z + b.z;
    float o3 = (v.w - mu) * inv * g.w + b.w;
    size_t base = (size_t)tok * DD + tid * 4;
    split_store2(g_xnh, g_xnl, base,     o0, o1);
    split_store2(g_xnh, g_xnl, base + 2, o2, o3);
}

// ------------------------------------------------------------ fused weight/rel split
__global__ __launch_bounds__(256) void split_all(const float* __restrict__ Wq,
                                                 const float* __restrict__ Wk,
                                                 const float* __restrict__ Wv,
                                                 const float* __restrict__ Wo,
                                                 const float* __restrict__ rel)
{
    int bid = blockIdx.x;
    if (bid < 1024) {
        int w = bid >> 8;
        const float* src = (w == 0) ? Wq : (w == 1) ? Wk : (w == 2) ? Wv : Wo;
        size_t i = ((size_t)(bid & 255) * 256 + threadIdx.x) * 4;
        float4 v = *reinterpret_cast<const float4*>(src + i);
        size_t o = (size_t)w * DD * DD + i;
        split_store2(g_wh, g_wl, o,     v.x, v.y);
        split_store2(g_wh, g_wl, o + 2, v.z, v.w);
    } else {
        int iv = (bid - 1024) * 256 + threadIdx.x;
        if (iv < RELN * DKK / 4) {
            size_t i = (size_t)iv * 4;
            float4 v = *reinterpret_cast<const float4*>(rel + i);
            split_store2(g_relh, g_rell, i,     v.x, v.y);
            split_store2(g_relh, g_rell, i + 2, v.z, v.w);
        }
    }
}

// ------------------------------------------------------------ pipelined fused GEMM (R5)
#define GS 40
#define PLG (128 * GS)
#define AH_OFF 0
#define AL_OFF (PLG * 2)
#define BH_OFF (PLG * 4)
#define BL_OFF (PLG * 6)
#define STAGE_B (PLG * 8)
#define GEMM_SMEM (2 * STAGE_B)

__global__ __launch_bounds__(256, 2) void gemm_tc_kernel(
    const __nv_bfloat16* __restrict__ Ah, const __nv_bfloat16* __restrict__ Al,
    const __nv_bfloat16* __restrict__ Wh, const __nv_bfloat16* __restrict__ Wl,
    const float* __restrict__ b0, const float* __restrict__ b1,
    const float* __restrict__ b2,
    float* __restrict__ CoutF, const float* __restrict__ res,
    __nv_bfloat16* __restrict__ Qh, __nv_bfloat16* __restrict__ Ql,
    __nv_bfloat16* __restrict__ Kh, __nv_bfloat16* __restrict__ Kl,
    __nv_bfloat16* __restrict__ Vh, __nv_bfloat16* __restrict__ Vl,
    int mode)
{
    extern __shared__ __align__(16) char smem[];
    const u32 sb = (u32)__cvta_generic_to_shared(smem);

    const int tid = threadIdx.x;
    const int lane = tid & 31, wid = tid >> 5;
    const int wm = wid & 1, wn = wid >> 1;
    const int m0 = blockIdx.y * 128;
    const int n0 = blockIdx.x * 128;

    const int lr = tid >> 2;
    const int lc = (tid & 3) << 3;

    float acc[4][4][4] = {};

    auto load_stage = [&](int k0, int s) {
        u32 base = sb + s * STAGE_B;
#pragma unroll
        for (int it = 0; it < 2; it++) {
            int r = lr + it * 64;
            u32 soff = (u32)(r * GS + lc) * 2;
            int mg = m0 + r;
            int mclamp = mg < NTOK ? mg : NTOK - 1;
            int sz = mg < NTOK ? 16 : 0;
            cpa16(base + AH_OFF + soff, &Ah[(size_t)mclamp * DD + k0 + lc], sz);
            cpa16(base + AL_OFF + soff, &Al[(size_t)mclamp * DD + k0 + lc], sz);
            int ng = n0 + r;
            cpa16(base + BH_OFF + soff, &Wh[(size_t)ng * DD + k0 + lc], 16);
            cpa16(base + BL_OFF + soff, &Wl[(size_t)ng * DD + k0 + lc], 16);
        }
        cp_commit();
    };

    load_stage(0, 0);

#pragma unroll 1
    for (int ks = 0; ks < 16; ks++) {
        if (ks + 1 < 16) load_stage((ks + 1) * 32, (ks + 1) & 1);
        if (ks + 1 < 16) cp_wait<1>(); else cp_wait<0>();
        __syncthreads();

        u32 base = sb + (ks & 1) * STAGE_B;
#pragma unroll
        for (int kt = 0; kt < 32; kt += 16) {
            u32 bfh[8], bfl[8];
            {
                int g = lane >> 3, r8 = lane & 7;
                int brow = wn * 32 + ((g >> 1) & 1) * 8 + r8;
                int bcol = kt + (g & 1) * 8;
                u32 boff = base + (u32)(brow * GS + bcol) * 2;
                ldsm4(&bfh[0], boff + BH_OFF);
                ldsm4(&bfh[4], boff + BH_OFF + 16 * GS * 2);
                ldsm4(&bfl[0], boff + BL_OFF);
                ldsm4(&bfl[4], boff + BL_OFF + 16 * GS * 2);
            }
#pragma unroll
            for (int mt = 0; mt < 4; mt++) {
                u32 afh[4], afl[4];
                int arow = wm * 64 + mt * 16 + (lane & 15);
                int acol = kt + ((lane >> 4) << 3);
                u32 aoff = base + (u32)(arow * GS + acol) * 2;
                ldsm4(afh, aoff + AH_OFF);
                ldsm4(afl, aoff + AL_OFF);
#pragma unroll
                for (int nt = 0; nt < 4; nt++) {
                    mma16816(acc[mt][nt], afh, &bfh[nt * 2]);
                    mma16816(acc[mt][nt], afh, &bfl[nt * 2]);
                    mma16816(acc[mt][nt], afl, &bfh[nt * 2]);
                }
            }
        }
        __syncthreads();
    }

    const int r = lane >> 2, c = (lane & 3) << 1;
    if (mode == 0) {
        int wsel = n0 >> 9;
        const float* bias = wsel == 0 ? b0 : (wsel == 1 ? b1 : b2);
        float scl = wsel == 1 ? 0.125f : 1.0f;
        __nv_bfloat16* OH = wsel == 0 ? Qh : (wsel == 1 ? Kh : Vh);
        __nv_bfloat16* OL = wsel == 0 ? Ql : (wsel == 1 ? Kl : Vl);
        int nl0 = (n0 & 511) + wn * 32;
#pragma unroll
        for (int mt = 0; mt < 4; mt++) {
#pragma unroll
            for (int nt = 0; nt < 4; nt++) {
                int nl = nl0 + nt * 8 + c;
                float bb0 = bias[nl], bb1 = bias[nl + 1];
                int h = nl >> 6, dd = nl & 63;
#pragma unroll
                for (int half = 0; half < 2; half++) {
                    int m = m0 + wm * 64 + mt * 16 + r + half * 8;
                    if (m >= NTOK) continue;
                    int bidx = m / LL, l = m - bidx * LL;
                    float ox = (acc[mt][nt][half * 2]     + bb0) * scl;
                    float oy = (acc[mt][nt][half * 2 + 1] + bb1) * scl;
                    size_t idx = ((size_t)(bidx * HH + h) * LL + l) * DKK + dd;
                    split_store2(OH, OL, idx, ox, oy);
                }
            }
        }
    } else {
#pragma unroll
        for (int mt = 0; mt < 4; mt++) {
#pragma unroll
            for (int nt = 0; nt < 4; nt++) {
                int n = n0 + wn * 32 + nt * 8 + c;
                float bb0 = b0[n], bb1 = b0[n + 1];
#pragma unroll
                for (int half = 0; half < 2; half++) {
                    int m = m0 + wm * 64 + mt * 16 + r + half * 8;
                    if (m >= NTOK) continue;
                    size_t off = (size_t)m * DD + n;
                    float2 r2 = *reinterpret_cast<const float2*>(&res[off]);
                    *reinterpret_cast<float2*>(&CoutF[off]) =
                        make_float2(acc[mt][nt][half * 2] + bb0 + r2.x,
                                    acc[mt][nt][half * 2 + 1] + bb1 + r2.y);
                }
            }
        }
    }
}

// --------------------------------------------------------- flash attention (R10 + Q-in-regs + 2-term PV)
#define SSTR 72
#define RSTR 132

#define AQH   0
#define AQL   9216
#define AKH   18432
#define AKL   27648
#define AVH   36864
#define AVL   46080
#define ARNH  55296
#define ARNL  64512
#define ARING 73728
#define ATTN_SMEM 107520

__global__ __launch_bounds__(256, 2) void attn_tc_kernel(
    const __nv_bfloat16* __restrict__ relh, const __nv_bfloat16* __restrict__ rell)
{
    extern __shared__ __align__(16) char smem[];
    __nv_bfloat16* sQh = (__nv_bfloat16*)(smem + AQH);
    __nv_bfloat16* sQl = (__nv_bfloat16*)(smem + AQL);
    float* sRing = (float*)(smem + ARING);

    const int tid = threadIdx.x;
    const int lane = tid & 31, wid = tid >> 5;
    const bool isq = wid < 4;
    const int wq = wid & 3;
    const int bh = blockIdx.y;
    const int i0 = blockIdx.x << 6;
    const u32 sb = (u32)__cvta_generic_to_shared(smem);
    const int g = lane >> 3, r8 = lane & 7;
    const int r4 = lane >> 2, c2 = (lane & 3) << 1;
    const int row0 = (wq << 4) + r4;

    const __nv_bfloat16* qh = g_qh + (size_t)bh * LL * DKK;
    const __nv_bfloat16* ql = g_ql + (size_t)bh * LL * DKK;
    const __nv_bfloat16* kh = g_kh + (size_t)bh * LL * DKK;
    const __nv_bfloat16* kl = g_kl + (size_t)bh * LL * DKK;
    const __nv_bfloat16* vh = g_vh + (size_t)bh * LL * DKK;
    const __nv_bfloat16* vl = g_vl + (size_t)bh * LL * DKK;

    // cp.async tile loaders (16B chunks, zero-fill out of range)
    auto cpa_k = [&](int j0) {
#pragma unroll
        for (int it = 0; it < 2; it++) {
            int idx = tid + (it << 8);
            int r = idx >> 3, c = (idx & 7) << 3;
            int jg = j0 + r;
            int jc = jg < LL ? jg : 0;
            int sz = jg < LL ? 16 : 0;
            u32 off = (u32)(r * SSTR + c) * 2;
            cpa16(sb + AKH + off, &kh[(size_t)jc * DKK + c], sz);
            cpa16(sb + AKL + off, &kl[(size_t)jc * DKK + c], sz);
        }
    };
    auto cpa_v = [&](int j0) {
#pragma unroll
        for (int it = 0; it < 2; it++) {
            int idx = tid + (it << 8);
            int r = idx >> 3, c = (idx & 7) << 3;
            int jg = j0 + r;
            int jc = jg < LL ? jg : 0;
            int sz = jg < LL ? 16 : 0;
            u32 off = (u32)(r * SSTR + c) * 2;
            cpa16(sb + AVH + off, &vh[(size_t)jc * DKK + c], sz);
            cpa16(sb + AVL + off, &vl[(size_t)jc * DKK + c], sz);
        }
    };
    auto cpa_rel = [&](int mstart) {
#pragma unroll
        for (int it = 0; it < 2; it++) {
            int idx = tid + (it << 8);
            int r = idx >> 3, c = (idx & 7) << 3;
            int mg = mstart + r;
            bool ok = (mg >= 0 && mg < RELN);
            int mc = ok ? mg : 0;
            int sz = ok ? 16 : 0;
            u32 off = (u32)(r * SSTR + c) * 2;
            cpa16(sb + ARNH + off, &relh[(size_t)mc * DKK + c], sz);
            cpa16(sb + ARNL + off, &rell[(size_t)mc * DKK + c], sz);
        }
    };

    // prologue group A: K(0) + ring-primer rel rows
    cpa_k(0);
    cpa_rel(936 - i0);
    cp_commit();

    // Q tile (regular loads, overlapped with group A)
#pragma unroll
    for (int it = 0; it < 2; it++) {
        int idx = tid + it * 256;
        int r = idx >> 3, c = (idx & 7) << 3;
        int rg = i0 + r;
        uint4 h4 = make_uint4(0,0,0,0), l4 = make_uint4(0,0,0,0);
        if (rg < LL) {
            h4 = *reinterpret_cast<const uint4*>(&qh[(size_t)rg * DKK + c]);
            l4 = *reinterpret_cast<const uint4*>(&ql[(size_t)rg * DKK + c]);
        }
        *reinterpret_cast<uint4*>(&sQh[r * SSTR + c]) = h4;
        *reinterpret_cast<uint4*>(&sQl[r * SSTR + c]) = l4;
    }

    float big[16][4] = {};
    float mrow[2] = {-1e30f, -1e30f};
    float lrow[2] = {0.f, 0.f};

    // Q fragments cached in registers (loaded once; used by S and R GEMMs)
    u32 qfh[4][4], qfl[4][4];

    auto gemm64 = [&](u32 bhof, u32 blof) {
#pragma unroll
        for (int q = 0; q < 8; q++)
            big[q][0] = big[q][1] = big[q][2] = big[q][3] = 0.f;
#pragma unroll
        for (int kc = 0; kc < 4; kc++) {
            int bcol = (kc << 4) + ((g & 1) << 3);
#pragma unroll
            for (int cb = 0; cb < 2; cb++) {
                u32 bh_[8], bl_[8];
                int brow = cb * 32 + ((g >> 1) & 1) * 8 + r8;
                u32 boff = (u32)(brow * SSTR + bcol) * 2;
                ldsm4(&bh_[0], sb + bhof + boff);
                ldsm4(&bh_[4], sb + bhof + boff + 16 * SSTR * 2);
                ldsm4(&bl_[0], sb + blof + boff);
                ldsm4(&bl_[4], sb + blof + boff + 16 * SSTR * 2);
#pragma unroll
                for (int nt2 = 0; nt2 < 4; nt2++) {
                    mma16816(big[cb * 4 + nt2], qfh[kc], &bh_[nt2 * 2]);
                    mma16816(big[cb * 4 + nt2], qfh[kc], &bl_[nt2 * 2]);
                    mma16816(big[cb * 4 + nt2], qfl[kc], &bh_[nt2 * 2]);
                }
            }
        }
    };
    auto ring_write = [&](int base_w) {
#pragma unroll
        for (int q = 0; q < 8; q++) {
            int col = base_w + (q << 3) + c2;
            *reinterpret_cast<float2*>(&sRing[row0 * RSTR + col]) =
                make_float2(big[q][0], big[q][1]);
            *reinterpret_cast<float2*>(&sRing[(row0 + 8) * RSTR + col]) =
                make_float2(big[q][2], big[q][3]);
        }
    };

    // prologue: Q frags + prime ring slots [0..63]
    cp_wait<0>();
    __syncthreads();
#pragma unroll
    for (int kc = 0; kc < 4; kc++) {
        int arow = (wq << 4) + (lane & 15);
        int acol = (kc << 4) + ((lane >> 4) << 3);
        u32 aoff = (u32)(arow * SSTR + acol) * 2;
        ldsm4(qfh[kc], sb + AQH + aoff);
        ldsm4(qfl[kc], sb + AQL + aoff);
    }
    if (!isq) {
        gemm64(ARNH, ARNL);
        ring_write(0);
    }
    __syncthreads();           // rel_new buffer consumed
    cpa_rel(0 - i0 + 1000);    // rel_new(0)
    cp_commit();

#pragma unroll 1
    for (int t = 0; t < 16; t++) {
        const int j0 = t << 6;
        __syncthreads();       // phase2(t-1) done: sV free, ring read slots free
        cpa_v(j0);
        cp_commit();
        cp_wait<0>();          // V(t) + prefetched {K(t), rel_new(t)}
        __syncthreads();

        // -------- phase 1: S (qwarps) | R_new -> ring (relwarps) --------
        if (isq) {
            gemm64(AKH, AKL);
        } else {
            gemm64(ARNH, ARNL);
            ring_write((64 * (t + 1)) & 127);
        }
        __syncthreads();       // phase-1 reads done: K and rel_new buffers free

        // prefetch next tile's K + rel_new during phase 2
        if (t + 1 < 16) {
            cpa_k((t + 1) << 6);
            cpa_rel(((t + 1) << 6) - i0 + 1000);
            cp_commit();
        }

        // -------- phase 2: softmax + PV (qwarps) --------
        if (isq) {
            const int bt = (t << 6) & 127;
            float mx0 = -1e30f, mx1 = -1e30f;
#pragma unroll
            for (int nt = 0; nt < 8; nt++) {
#pragma unroll
                for (int k = 0; k < 2; k++) {
                    int c = (nt << 3) + c2 + k;
                    int s0 = (bt + c - row0 + 63) & 127;
                    int s1 = (bt + c - row0 - 8 + 63) & 127;
                    float v0 = big[nt][k]     + sRing[row0 * RSTR + s0];
                    float v1 = big[nt][2 + k] + sRing[(row0 + 8) * RSTR + s1];
                    bool valid = (j0 + c) < LL;
                    v0 = valid ? v0 : -1e30f;
                    v1 = valid ? v1 : -1e30f;
                    big[nt][k] = v0; big[nt][2 + k] = v1;
                    mx0 = fmaxf(mx0, v0);
                    mx1 = fmaxf(mx1, v1);
                }
            }
            mx0 = fmaxf(mx0, __shfl_xor_sync(0xffffffffu, mx0, 1));
            mx0 = fmaxf(mx0, __shfl_xor_sync(0xffffffffu, mx0, 2));
            mx1 = fmaxf(mx1, __shfl_xor_sync(0xffffffffu, mx1, 1));
            mx1 = fmaxf(mx1, __shfl_xor_sync(0xffffffffu, mx1, 2));
            float m0n = fmaxf(mrow[0], mx0);
            float m1n = fmaxf(mrow[1], mx1);
            float corr0 = __expf(mrow[0] - m0n);
            float corr1 = __expf(mrow[1] - m1n);
            mrow[0] = m0n; mrow[1] = m1n;
            float s0 = 0.f, s1 = 0.f;
#pragma unroll
            for (int nt = 0; nt < 8; nt++) {
                float p0 = __expf(big[nt][0] - m0n);
                float p1 = __expf(big[nt][1] - m0n);
                float p2 = __expf(big[nt][2] - m1n);
                float p3 = __expf(big[nt][3] - m1n);
                big[nt][0] = p0; big[nt][1] = p1; big[nt][2] = p2; big[nt][3] = p3;
                s0 += p0 + p1; s1 += p2 + p3;
                big[8 + nt][0] *= corr0; big[8 + nt][1] *= corr0;
                big[8 + nt][2] *= corr1; big[8 + nt][3] *= corr1;
            }
            s0 += __shfl_xor_sync(0xffffffffu, s0, 1);
            s0 += __shfl_xor_sync(0xffffffffu, s0, 2);
            s1 += __shfl_xor_sync(0xffffffffu, s1, 1);
            s1 += __shfl_xor_sync(0xffffffffu, s1, 2);
            lrow[0] = lrow[0] * corr0 + s0;
            lrow[1] = lrow[1] * corr1 + s1;

            // PV with register P (hi plane only: Ph·Vh + Ph·Vl)
#pragma unroll
            for (int kc = 0; kc < 4; kc++) {
                u32 pfh[4];
                pfh[0] = pack_h(big[2*kc][0],   big[2*kc][1]);
                pfh[1] = pack_h(big[2*kc][2],   big[2*kc][3]);
                pfh[2] = pack_h(big[2*kc+1][0], big[2*kc+1][1]);
                pfh[3] = pack_h(big[2*kc+1][2], big[2*kc+1][3]);
#pragma unroll
                for (int vcb = 0; vcb < 2; vcb++) {
                    u32 vh_[8], vl_[8];
                    int vrow = (kc << 4) + ((g & 1) << 3) + r8;
                    int vcol = (vcb << 5) + (((g >> 1) & 1) << 3);
                    u32 voff = (u32)(vrow * SSTR + vcol) * 2;
                    ldsm4t(&vh_[0], sb + AVH + voff);
                    ldsm4t(&vh_[4], sb + AVH + voff + 32);
                    ldsm4t(&vl_[0], sb + AVL + voff);
                    ldsm4t(&vl_[4], sb + AVL + voff + 32);
#pragma unroll
                    for (int nt2 = 0; nt2 < 4; nt2++) {
                        float* oa = big[8 + vcb * 4 + nt2];
                        mma16816(oa, pfh, &vh_[nt2 * 2]);
                        mma16816(oa, pfh, &vl_[nt2 * 2]);
                    }
                }
            }
        }
    }

    // epilogue (qwarps): normalize + split-store ctx
    if (isq) {
        int b = bh >> 3, h = bh & 7;
        float li0 = 1.0f / lrow[0];
        float li1 = 1.0f / lrow[1];
        int rg0 = i0 + row0, rg1 = rg0 + 8;
#pragma unroll
        for (int nt = 0; nt < 8; nt++) {
            int col = h * 64 + (nt << 3) + c2;
            if (rg0 < LL)
                split_store2(g_cth, g_ctl, ((size_t)(b * LL + rg0)) * DD + col,
                             big[8 + nt][0] * li0, big[8 + nt][1] * li0);
            if (rg1 < LL)
                split_store2(g_cth, g_ctl, ((size_t)(b * LL + rg1)) * DD + col,
                             big[8 + nt][2] * li1, big[8 + nt][3] * li1);
        }
    }
}

// ---------------------------------------------------------------- launcher
extern "C" void kernel_launch(void* const* d_in, const int* in_sizes, int n_in,
                              void* d_out, int out_size)
{
    const float* x     = (const float*)d_in[0];
    const float* Wq    = (const float*)d_in[1];
    const float* bq    = (const float*)d_in[2];
    const float* Wk    = (const float*)d_in[3];
    const float* bk    = (const float*)d_in[4];
    const float* Wv    = (const float*)d_in[5];
    const float* bv    = (const float*)d_in[6];
    const float* Wo    = (const float*)d_in[7];
    const float* bo    = (const float*)d_in[8];
    const float* rel   = (const float*)d_in[9];
    const float* gamma = (const float*)d_in[10];
    const float* beta  = (const float*)d_in[11];
    float* out = (float*)d_out;

    __nv_bfloat16 *xnh, *xnl, *qh, *ql, *kh, *kl, *vh, *vl, *cth, *ctl, *wh, *wl, *relh, *rell;
    cudaGetSymbolAddress((void**)&xnh, g_xnh);
    cudaGetSymbolAddress((void**)&xnl, g_xnl);
    cudaGetSymbolAddress((void**)&qh,  g_qh);
    cudaGetSymbolAddress((void**)&ql,  g_ql);
    cudaGetSymbolAddress((void**)&kh,  g_kh);
    cudaGetSymbolAddress((void**)&kl,  g_kl);
    cudaGetSymbolAddress((void**)&vh,  g_vh);
    cudaGetSymbolAddress((void**)&vl,  g_vl);
    cudaGetSymbolAddress((void**)&cth, g_cth);
    cudaGetSymbolAddress((void**)&ctl, g_ctl);
    cudaGetSymbolAddress((void**)&wh,  g_wh);
    cudaGetSymbolAddress((void**)&wl,  g_wl);
    cudaGetSymbolAddress((void**)&relh, g_relh);
    cudaGetSymbolAddress((void**)&rell, g_rell);

    cudaFuncSetAttribute(attn_tc_kernel, cudaFuncAttributeMaxDynamicSharedMemorySize,
                         ATTN_SMEM);
    cudaFuncSetAttribute(gemm_tc_kernel, cudaFuncAttributeMaxDynamicSharedMemorySize,
                         GEMM_SMEM);

    // ln (s0) || weight/rel split (s2), then join — capture-safe (proven R9/R10)
    cudaStream_t s2;
    cudaStreamCreateWithFlags(&s2, cudaStreamNonBlocking);
    cudaEvent_t eFork, eWs;
    cudaEventCreateWithFlags(&eFork, cudaEventDisableTiming);
    cudaEventCreateWithFlags(&eWs,   cudaEventDisableTiming);
    cudaEventRecord(eFork, 0);
    cudaStreamWaitEvent(s2, eFork, 0);
    ln_kernel<<<NTOK, 128>>>(x, gamma, beta);
    split_all<<<1149, 256, 0, s2>>>(Wq, Wk, Wv, Wo, rel);
    cudaEventRecord(eWs, s2);
    cudaStreamWaitEvent(0, eWs, 0);

    // fused QKV
    dim3 gq(1536 / 128, (NTOK + 127) / 128);  // (12, 63)
    gemm_tc_kernel<<<gq, 256, GEMM_SMEM>>>(xnh, xnl, wh, wl, bq, bk, bv,
                                           nullptr, nullptr,
                                           qh, ql, kh, kl, vh, vl, 0);

    dim3 ga((LL + 63) / 64, BB * HH);  // (16, 64)
    attn_tc_kernel<<<ga, 256, ATTN_SMEM>>>(relh, rell);

    dim3 go(DD / 128, (NTOK + 127) / 128);    // (4, 63)
    gemm_tc_kernel<<<go, 256, GEMM_SMEM>>>(cth, ctl, wh + 3*DD*DD, wl + 3*DD*DD,
                                           bo, nullptr, nullptr,
                                           out, x,
                                           nullptr, nullptr, nullptr, nullptr,
                                           nullptr, nullptr, 1);
}

// round 14
// speedup vs baseline: 1.0775x; 1.0255x over previous
#include <cuda_runtime.h>
#include <cuda_bf16.h>
#include <math.h>

#define BB 8
#define LL 1000
#define DD 512
#define HH 8
#define DKK 64
#define NTOK (BB*LL)
#define RELN (2*LL-1)

typedef unsigned int u32;

// ------------------------------------------------------------ scratch (bf16 hi/lo planes)
__device__ __nv_bfloat16 g_xnh[NTOK*DD];
__device__ __nv_bfloat16 g_xnl[NTOK*DD];
__device__ __nv_bfloat16 g_qh[NTOK*DD];  // (B,H,L,dk)
__device__ __nv_bfloat16 g_ql[NTOK*DD];
__device__ __nv_bfloat16 g_kh[NTOK*DD];  // pre-scaled by 1/8
__device__ __nv_bfloat16 g_kl[NTOK*DD];
__device__ __nv_bfloat16 g_vh[NTOK*DD];
__device__ __nv_bfloat16 g_vl[NTOK*DD];
__device__ __nv_bfloat16 g_cth[NTOK*DD]; // ctx (B,L,D)
__device__ __nv_bfloat16 g_ctl[NTOK*DD];
__device__ __nv_bfloat16 g_wh[4*DD*DD];  // [Wq;Wk;Wv;Wo] hi
__device__ __nv_bfloat16 g_wl[4*DD*DD];
__device__ __nv_bfloat16 g_relh[RELN*DKK];
__device__ __nv_bfloat16 g_rell[RELN*DKK];

// ------------------------------------------------------------ asm helpers
__device__ __forceinline__ void mma16816(float* d, const u32* a, const u32* b) {
    asm volatile(
        "mma.sync.aligned.m16n8k16.row.col.f32.bf16.bf16.f32 "
        "{%0,%1,%2,%3}, {%4,%5,%6,%7}, {%8,%9}, {%0,%1,%2,%3};"
        : "+f"(d[0]), "+f"(d[1]), "+f"(d[2]), "+f"(d[3])
        : "r"(a[0]), "r"(a[1]), "r"(a[2]), "r"(a[3]), "r"(b[0]), "r"(b[1]));
}
__device__ __forceinline__ void ldsm4(u32* r, u32 addr) {
    asm volatile("ldmatrix.sync.aligned.m8n8.x4.shared.b16 {%0,%1,%2,%3}, [%4];"
                 : "=r"(r[0]), "=r"(r[1]), "=r"(r[2]), "=r"(r[3]) : "r"(addr));
}
__device__ __forceinline__ void ldsm4t(u32* r, u32 addr) {
    asm volatile("ldmatrix.sync.aligned.m8n8.x4.trans.shared.b16 {%0,%1,%2,%3}, [%4];"
                 : "=r"(r[0]), "=r"(r[1]), "=r"(r[2]), "=r"(r[3]) : "r"(addr));
}
__device__ __forceinline__ void cpa16(u32 dst, const void* src, int sz) {
    asm volatile("cp.async.cg.shared.global [%0], [%1], 16, %2;"
                 :: "r"(dst), "l"(src), "r"(sz));
}
__device__ __forceinline__ void cp_commit() {
    asm volatile("cp.async.commit_group;");
}
template <int N> __device__ __forceinline__ void cp_wait() {
    asm volatile("cp.async.wait_group %0;" :: "n"(N));
}
__device__ __forceinline__ void split_store2(__nv_bfloat16* H, __nv_bfloat16* L,
                                             size_t idx, float x, float y) {
    __nv_bfloat16 hx = __float2bfloat16_rn(x), hy = __float2bfloat16_rn(y);
    *reinterpret_cast<__nv_bfloat162*>(&H[idx]) = __halves2bfloat162(hx, hy);
    *reinterpret_cast<__nv_bfloat162*>(&L[idx]) = __halves2bfloat162(
        __float2bfloat16_rn(x - __bfloat162float(hx)),
        __float2bfloat16_rn(y - __bfloat162float(hy)));
}
__device__ __forceinline__ u32 pack_h(float x, float y) {
    __nv_bfloat162 hv = __halves2bfloat162(__float2bfloat16_rn(x),
                                           __float2bfloat16_rn(y));
    return *reinterpret_cast<u32*>(&hv);
}

// ------------------------------------------------------------ LayerNorm + bf16 split
__global__ __launch_bounds__(128) void ln_kernel(const float* __restrict__ x,
                                                 const float* __restrict__ gamma,
                                                 const float* __restrict__ beta)
{
    int tok = blockIdx.x;
    int tid = threadIdx.x;
    const float4 v = reinterpret_cast<const float4*>(x + (size_t)tok * DD)[tid];
    float s  = v.x + v.y + v.z + v.w;
    float ss = v.x*v.x + v.y*v.y + v.z*v.z + v.w*v.w;
#pragma unroll
    for (int o = 16; o; o >>= 1) {
        s  += __shfl_xor_sync(0xffffffffu, s,  o);
        ss += __shfl_xor_sync(0xffffffffu, ss, o);
    }
    __shared__ float sh[8];
    int w = tid >> 5, lane = tid & 31;
    if (lane == 0) { sh[w] = s; sh[4 + w] = ss; }
    __syncthreads();
    s  = sh[0] + sh[1] + sh[2] + sh[3];
    ss = sh[4] + sh[5] + sh[6] + sh[7];
    float mu  = s * (1.0f / DD);
    float var = ss * (1.0f / DD) - mu * mu;
    float inv = rsqrtf(var + 1e-5f);
    float4 g = reinterpret_cast<const float4*>(gamma)[tid];
    float4 b = reinterpret_cast<const float4*>(beta)[tid];
    float o0 = (v.x - mu) * inv * g.x + b.x;
    float o1 = (v.y - mu) * inv * g.y + b.y;
    float o2 = (v.z - mu) * inv * g.z + b.z;
    float o3 = (v.w - mu) * inv * g.w + b.w;
    size_t base = (size_t)tok * DD + tid * 4;
    split_store2(g_xnh, g_xnl, base,     o0, o1);
    split_store2(g_xnh, g_xnl, base + 2, o2, o3);
}

// ------------------------------------------------------------ fused weight/rel split
__global__ __launch_bounds__(256) void split_all(const float* __restrict__ Wq,
                                                 const float* __restrict__ Wk,
                                                 const float* __restrict__ Wv,
                                                 const float* __restrict__ Wo,
                                                 const float* __restrict__ rel)
{
    int bid = blockIdx.x;
    if (bid < 1024) {
        int w = bid >> 8;
        const float* src = (w == 0) ? Wq : (w == 1) ? Wk : (w == 2) ? Wv : Wo;
        size_t i = ((size_t)(bid & 255) * 256 + threadIdx.x) * 4;
        float4 v = *reinterpret_cast<const float4*>(src + i);
        size_t o = (size_t)w * DD * DD + i;
        split_store2(g_wh, g_wl, o,     v.x, v.y);
        split_store2(g_wh, g_wl, o + 2, v.z, v.w);
    } else {
        int iv = (bid - 1024) * 256 + threadIdx.x;
        if (iv < RELN * DKK / 4) {
            size_t i = (size_t)iv * 4;
            float4 v = *reinterpret_cast<const float4*>(rel + i);
            split_store2(g_relh, g_rell, i,     v.x, v.y);
            split_store2(g_relh, g_rell, i + 2, v.z, v.w);
        }
    }
}

// ------------------------------------------------------------ pipelined fused GEMM (R5)
#define GS 40
#define PLG (128 * GS)
#define AH_OFF 0
#define AL_OFF (PLG * 2)
#define BH_OFF (PLG * 4)
#define BL_OFF (PLG * 6)
#define STAGE_B (PLG * 8)
#define GEMM_SMEM (2 * STAGE_B)

__global__ __launch_bounds__(256, 2) void gemm_tc_kernel(
    const __nv_bfloat16* __restrict__ Ah, const __nv_bfloat16* __restrict__ Al,
    const __nv_bfloat16* __restrict__ Wh, const __nv_bfloat16* __restrict__ Wl,
    const float* __restrict__ b0, const float* __restrict__ b1,
    const float* __restrict__ b2,
    float* __restrict__ CoutF, const float* __restrict__ res,
    __nv_bfloat16* __restrict__ Qh, __nv_bfloat16* __restrict__ Ql,
    __nv_bfloat16* __restrict__ Kh, __nv_bfloat16* __restrict__ Kl,
    __nv_bfloat16* __restrict__ Vh, __nv_bfloat16* __restrict__ Vl,
    int mode)
{
    extern __shared__ __align__(16) char smem[];
    const u32 sb = (u32)__cvta_generic_to_shared(smem);

    const int tid = threadIdx.x;
    const int lane = tid & 31, wid = tid >> 5;
    const int wm = wid & 1, wn = wid >> 1;
    const int m0 = blockIdx.y * 128;
    const int n0 = blockIdx.x * 128;

    const int lr = tid >> 2;
    const int lc = (tid & 3) << 3;

    float acc[4][4][4] = {};

    auto load_stage = [&](int k0, int s) {
        u32 base = sb + s * STAGE_B;
#pragma unroll
        for (int it = 0; it < 2; it++) {
            int r = lr + it * 64;
            u32 soff = (u32)(r * GS + lc) * 2;
            int mg = m0 + r;
            int mclamp = mg < NTOK ? mg : NTOK - 1;
            int sz = mg < NTOK ? 16 : 0;
            cpa16(base + AH_OFF + soff, &Ah[(size_t)mclamp * DD + k0 + lc], sz);
            cpa16(base + AL_OFF + soff, &Al[(size_t)mclamp * DD + k0 + lc], sz);
            int ng = n0 + r;
            cpa16(base + BH_OFF + soff, &Wh[(size_t)ng * DD + k0 + lc], 16);
            cpa16(base + BL_OFF + soff, &Wl[(size_t)ng * DD + k0 + lc], 16);
        }
        cp_commit();
    };

    load_stage(0, 0);

#pragma unroll 1
    for (int ks = 0; ks < 16; ks++) {
        if (ks + 1 < 16) load_stage((ks + 1) * 32, (ks + 1) & 1);
        if (ks + 1 < 16) cp_wait<1>(); else cp_wait<0>();
        __syncthreads();

        u32 base = sb + (ks & 1) * STAGE_B;
#pragma unroll
        for (int kt = 0; kt < 32; kt += 16) {
            u32 bfh[8], bfl[8];
            {
                int g = lane >> 3, r8 = lane & 7;
                int brow = wn * 32 + ((g >> 1) & 1) * 8 + r8;
                int bcol = kt + (g & 1) * 8;
                u32 boff = base + (u32)(brow * GS + bcol) * 2;
                ldsm4(&bfh[0], boff + BH_OFF);
                ldsm4(&bfh[4], boff + BH_OFF + 16 * GS * 2);
                ldsm4(&bfl[0], boff + BL_OFF);
                ldsm4(&bfl[4], boff + BL_OFF + 16 * GS * 2);
            }
#pragma unroll
            for (int mt = 0; mt < 4; mt++) {
                u32 afh[4], afl[4];
                int arow = wm * 64 + mt * 16 + (lane & 15);
                int acol = kt + ((lane >> 4) << 3);
                u32 aoff = base + (u32)(arow * GS + acol) * 2;
                ldsm4(afh, aoff + AH_OFF);
                ldsm4(afl, aoff + AL_OFF);
#pragma unroll
                for (int nt = 0; nt < 4; nt++) {
                    mma16816(acc[mt][nt], afh, &bfh[nt * 2]);
                    mma16816(acc[mt][nt], afh, &bfl[nt * 2]);
                    mma16816(acc[mt][nt], afl, &bfh[nt * 2]);
                }
            }
        }
        __syncthreads();
    }

    const int r = lane >> 2, c = (lane & 3) << 1;
    if (mode == 0) {
        int wsel = n0 >> 9;
        const float* bias = wsel == 0 ? b0 : (wsel == 1 ? b1 : b2);
        float scl = wsel == 1 ? 0.125f : 1.0f;
        __nv_bfloat16* OH = wsel == 0 ? Qh : (wsel == 1 ? Kh : Vh);
        __nv_bfloat16* OL = wsel == 0 ? Ql : (wsel == 1 ? Kl : Vl);
        int nl0 = (n0 & 511) + wn * 32;
#pragma unroll
        for (int mt = 0; mt < 4; mt++) {
#pragma unroll
            for (int nt = 0; nt < 4; nt++) {
                int nl = nl0 + nt * 8 + c;
                float bb0 = bias[nl], bb1 = bias[nl + 1];
                int h = nl >> 6, dd = nl & 63;
#pragma unroll
                for (int half = 0; half < 2; half++) {
                    int m = m0 + wm * 64 + mt * 16 + r + half * 8;
                    if (m >= NTOK) continue;
                    int bidx = m / LL, l = m - bidx * LL;
                    float ox = (acc[mt][nt][half * 2]     + bb0) * scl;
                    float oy = (acc[mt][nt][half * 2 + 1] + bb1) * scl;
                    size_t idx = ((size_t)(bidx * HH + h) * LL + l) * DKK + dd;
                    split_store2(OH, OL, idx, ox, oy);
                }
            }
        }
    } else {
#pragma unroll
        for (int mt = 0; mt < 4; mt++) {
#pragma unroll
            for (int nt = 0; nt < 4; nt++) {
                int n = n0 + wn * 32 + nt * 8 + c;
                float bb0 = b0[n], bb1 = b0[n + 1];
#pragma unroll
                for (int half = 0; half < 2; half++) {
                    int m = m0 + wm * 64 + mt * 16 + r + half * 8;
                    if (m >= NTOK) continue;
                    size_t off = (size_t)m * DD + n;
                    float2 r2 = *reinterpret_cast<const float2*>(&res[off]);
                    *reinterpret_cast<float2*>(&CoutF[off]) =
                        make_float2(acc[mt][nt][half * 2] + bb0 + r2.x,
                                    acc[mt][nt][half * 2 + 1] + bb1 + r2.y);
                }
            }
        }
    }
}

// --------------------------------------------------------- flash attention (R13 + V-latency hiding)
#define SSTR 72
#define RSTR 132

#define AQH   0
#define AQL   9216
#define AKH   18432
#define AKL   27648
#define AVH   36864
#define AVL   46080
#define ARNH  55296
#define ARNL  64512
#define ARING 73728
#define ATTN_SMEM 107520

__global__ __launch_bounds__(256, 2) void attn_tc_kernel(
    const __nv_bfloat16* __restrict__ relh, const __nv_bfloat16* __restrict__ rell)
{
    extern __shared__ __align__(16) char smem[];
    __nv_bfloat16* sQh = (__nv_bfloat16*)(smem + AQH);
    __nv_bfloat16* sQl = (__nv_bfloat16*)(smem + AQL);
    float* sRing = (float*)(smem + ARING);

    const int tid = threadIdx.x;
    const int lane = tid & 31, wid = tid >> 5;
    const bool isq = wid < 4;
    const int wq = wid & 3;
    const int bh = blockIdx.y;
    const int i0 = blockIdx.x << 6;
    const u32 sb = (u32)__cvta_generic_to_shared(smem);
    const int g = lane >> 3, r8 = lane & 7;
    const int r4 = lane >> 2, c2 = (lane & 3) << 1;
    const int row0 = (wq << 4) + r4;

    const __nv_bfloat16* qh = g_qh + (size_t)bh * LL * DKK;
    const __nv_bfloat16* ql = g_ql + (size_t)bh * LL * DKK;
    const __nv_bfloat16* kh = g_kh + (size_t)bh * LL * DKK;
    const __nv_bfloat16* kl = g_kl + (size_t)bh * LL * DKK;
    const __nv_bfloat16* vh = g_vh + (size_t)bh * LL * DKK;
    const __nv_bfloat16* vl = g_vl + (size_t)bh * LL * DKK;

    // cp.async tile loaders (16B chunks, zero-fill out of range)
    auto cpa_k = [&](int j0) {
#pragma unroll
        for (int it = 0; it < 2; it++) {
            int idx = tid + (it << 8);
            int r = idx >> 3, c = (idx & 7) << 3;
            int jg = j0 + r;
            int jc = jg < LL ? jg : 0;
            int sz = jg < LL ? 16 : 0;
            u32 off = (u32)(r * SSTR + c) * 2;
            cpa16(sb + AKH + off, &kh[(size_t)jc * DKK + c], sz);
            cpa16(sb + AKL + off, &kl[(size_t)jc * DKK + c], sz);
        }
    };
    auto cpa_v = [&](int j0) {
#pragma unroll
        for (int it = 0; it < 2; it++) {
            int idx = tid + (it << 8);
            int r = idx >> 3, c = (idx & 7) << 3;
            int jg = j0 + r;
            int jc = jg < LL ? jg : 0;
            int sz = jg < LL ? 16 : 0;
            u32 off = (u32)(r * SSTR + c) * 2;
            cpa16(sb + AVH + off, &vh[(size_t)jc * DKK + c], sz);
            cpa16(sb + AVL + off, &vl[(size_t)jc * DKK + c], sz);
        }
    };
    auto cpa_rel = [&](int mstart) {
#pragma unroll
        for (int it = 0; it < 2; it++) {
            int idx = tid + (it << 8);
            int r = idx >> 3, c = (idx & 7) << 3;
            int mg = mstart + r;
            bool ok = (mg >= 0 && mg < RELN);
            int mc = ok ? mg : 0;
            int sz = ok ? 16 : 0;
            u32 off = (u32)(r * SSTR + c) * 2;
            cpa16(sb + ARNH + off, &relh[(size_t)mc * DKK + c], sz);
            cpa16(sb + ARNL + off, &rell[(size_t)mc * DKK + c], sz);
        }
    };

    // prologue group A: K(0) + ring-primer rel rows
    cpa_k(0);
    cpa_rel(936 - i0);
    cp_commit();

    // Q tile (regular loads, overlapped with group A)
#pragma unroll
    for (int it = 0; it < 2; it++) {
        int idx = tid + it * 256;
        int r = idx >> 3, c = (idx & 7) << 3;
        int rg = i0 + r;
        uint4 h4 = make_uint4(0,0,0,0), l4 = make_uint4(0,0,0,0);
        if (rg < LL) {
            h4 = *reinterpret_cast<const uint4*>(&qh[(size_t)rg * DKK + c]);
            l4 = *reinterpret_cast<const uint4*>(&ql[(size_t)rg * DKK + c]);
        }
        *reinterpret_cast<uint4*>(&sQh[r * SSTR + c]) = h4;
        *reinterpret_cast<uint4*>(&sQl[r * SSTR + c]) = l4;
    }

    float big[16][4] = {};
    float mrow[2] = {-1e30f, -1e30f};
    float lrow[2] = {0.f, 0.f};

    // Q fragments cached in registers (loaded once; used by S and R GEMMs)
    u32 qfh[4][4], qfl[4][4];

    auto gemm64 = [&](u32 bhof, u32 blof) {
#pragma unroll
        for (int q = 0; q < 8; q++)
            big[q][0] = big[q][1] = big[q][2] = big[q][3] = 0.f;
#pragma unroll
        for (int kc = 0; kc < 4; kc++) {
            int bcol = (kc << 4) + ((g & 1) << 3);
#pragma unroll
            for (int cb = 0; cb < 2; cb++) {
                u32 bh_[8], bl_[8];
                int brow = cb * 32 + ((g >> 1) & 1) * 8 + r8;
                u32 boff = (u32)(brow * SSTR + bcol) * 2;
                ldsm4(&bh_[0], sb + bhof + boff);
                ldsm4(&bh_[4], sb + bhof + boff + 16 * SSTR * 2);
                ldsm4(&bl_[0], sb + blof + boff);
                ldsm4(&bl_[4], sb + blof + boff + 16 * SSTR * 2);
#pragma unroll
                for (int nt2 = 0; nt2 < 4; nt2++) {
                    mma16816(big[cb * 4 + nt2], qfh[kc], &bh_[nt2 * 2]);
                    mma16816(big[cb * 4 + nt2], qfh[kc], &bl_[nt2 * 2]);
                    mma16816(big[cb * 4 + nt2], qfl[kc], &bh_[nt2 * 2]);
                }
            }
        }
    };
    auto ring_write = [&](int base_w) {
#pragma unroll
        for (int q = 0; q < 8; q++) {
            int col = base_w + (q << 3) + c2;
            *reinterpret_cast<float2*>(&sRing[row0 * RSTR + col]) =
                make_float2(big[q][0], big[q][1]);
            *reinterpret_cast<float2*>(&sRing[(row0 + 8) * RSTR + col]) =
                make_float2(big[q][2], big[q][3]);
        }
    };

    // prologue: Q frags + prime ring slots [0..63]
    cp_wait<0>();
    __syncthreads();
#pragma unroll
    for (int kc = 0; kc < 4; kc++) {
        int arow = (wq << 4) + (lane & 15);
        int acol = (kc << 4) + ((lane >> 4) << 3);
        u32 aoff = (u32)(arow * SSTR + acol) * 2;
        ldsm4(qfh[kc], sb + AQH + aoff);
        ldsm4(qfl[kc], sb + AQL + aoff);
    }
    if (!isq) {
        gemm64(ARNH, ARNL);
        ring_write(0);
    }
    __syncthreads();           // rel_new buffer consumed
    cpa_rel(0 - i0 + 1000);    // rel_new(0)
    cp_commit();

#pragma unroll 1
    for (int t = 0; t < 16; t++) {
        const int j0 = t << 6;
        __syncthreads();       // syncA: phase2(t-1) done: sV free, ring read slots free
        cpa_v(j0);
        cp_commit();
        cp_wait<1>();          // wait ONLY for K(t)+rel_new(t); V(t) stays in flight
        __syncthreads();       // syncB

        // -------- phase 1: S (qwarps) | R_new -> ring (relwarps); V flies underneath --------
        if (isq) {
            gemm64(AKH, AKL);
        } else {
            gemm64(ARNH, ARNL);
            ring_write((64 * (t + 1)) & 127);
        }
        cp_wait<0>();          // V(t) arrived (hidden under phase 1)
        __syncthreads();       // syncC: ring + V visible; K/rel buffers free

        // prefetch next tile's K + rel_new during phase 2
        if (t + 1 < 16) {
            cpa_k((t + 1) << 6);
            cpa_rel(((t + 1) << 6) - i0 + 1000);
            cp_commit();
        }

        // -------- phase 2: softmax + PV (qwarps) --------
        if (isq) {
            const int bt = (t << 6) & 127;
            float mx0 = -1e30f, mx1 = -1e30f;
#pragma unroll
            for (int nt = 0; nt < 8; nt++) {
#pragma unroll
                for (int k = 0; k < 2; k++) {
                    int c = (nt << 3) + c2 + k;
                    int s0 = (bt + c - row0 + 63) & 127;
                    int s1 = (bt + c - row0 - 8 + 63) & 127;
                    float v0 = big[nt][k]     + sRing[row0 * RSTR + s0];
                    float v1 = big[nt][2 + k] + sRing[(row0 + 8) * RSTR + s1];
                    bool valid = (j0 + c) < LL;
                    v0 = valid ? v0 : -1e30f;
                    v1 = valid ? v1 : -1e30f;
                    big[nt][k] = v0; big[nt][2 + k] = v1;
                    mx0 = fmaxf(mx0, v0);
                    mx1 = fmaxf(mx1, v1);
                }
            }
            mx0 = fmaxf(mx0, __shfl_xor_sync(0xffffffffu, mx0, 1));
            mx0 = fmaxf(mx0, __shfl_xor_sync(0xffffffffu, mx0, 2));
            mx1 = fmaxf(mx1, __shfl_xor_sync(0xffffffffu, mx1, 1));
            mx1 = fmaxf(mx1, __shfl_xor_sync(0xffffffffu, mx1, 2));
            float m0n = fmaxf(mrow[0], mx0);
            float m1n = fmaxf(mrow[1], mx1);
            float corr0 = __expf(mrow[0] - m0n);
            float corr1 = __expf(mrow[1] - m1n);
            mrow[0] = m0n; mrow[1] = m1n;
            float s0 = 0.f, s1 = 0.f;
#pragma unroll
            for (int nt = 0; nt < 8; nt++) {
                float p0 = __expf(big[nt][0] - m0n);
                float p1 = __expf(big[nt][1] - m0n);
                float p2 = __expf(big[nt][2] - m1n);
                float p3 = __expf(big[nt][3] - m1n);
                big[nt][0] = p0; big[nt][1] = p1; big[nt][2] = p2; big[nt][3] = p3;
                s0 += p0 + p1; s1 += p2 + p3;
                big[8 + nt][0] *= corr0; big[8 + nt][1] *= corr0;
                big[8 + nt][2] *= corr1; big[8 + nt][3] *= corr1;
            }
            s0 += __shfl_xor_sync(0xffffffffu, s0, 1);
            s0 += __shfl_xor_sync(0xffffffffu, s0, 2);
            s1 += __shfl_xor_sync(0xffffffffu, s1, 1);
            s1 += __shfl_xor_sync(0xffffffffu, s1, 2);
            lrow[0] = lrow[0] * corr0 + s0;
            lrow[1] = lrow[1] * corr1 + s1;

            // PV with register P (hi plane only: Ph·Vh + Ph·Vl)
#pragma unroll
            for (int kc = 0; kc < 4; kc++) {
                u32 pfh[4];
                pfh[0] = pack_h(big[2*kc][0],   big[2*kc][1]);
                pfh[1] = pack_h(big[2*kc][2],   big[2*kc][3]);
                pfh[2] = pack_h(big[2*kc+1][0], big[2*kc+1][1]);
                pfh[3] = pack_h(big[2*kc+1][2], big[2*kc+1][3]);
#pragma unroll
                for (int vcb = 0; vcb < 2; vcb++) {
                    u32 vh_[8], vl_[8];
                    int vrow = (kc << 4) + ((g & 1) << 3) + r8;
                    int vcol = (vcb << 5) + (((g >> 1) & 1) << 3);
                    u32 voff = (u32)(vrow * SSTR + vcol) * 2;
                    ldsm4t(&vh_[0], sb + AVH + voff);
                    ldsm4t(&vh_[4], sb + AVH + voff + 32);
                    ldsm4t(&vl_[0], sb + AVL + voff);
                    ldsm4t(&vl_[4], sb + AVL + voff + 32);
#pragma unroll
                    for (int nt2 = 0; nt2 < 4; nt2++) {
                        float* oa = big[8 + vcb * 4 + nt2];
                        mma16816(oa, pfh, &vh_[nt2 * 2]);
                        mma16816(oa, pfh, &vl_[nt2 * 2]);
                    }
                }
            }
        }
    }

    // epilogue (qwarps): normalize + split-store ctx
    if (isq) {
        int b = bh >> 3, h = bh & 7;
        float li0 = 1.0f / lrow[0];
        float li1 = 1.0f / lrow[1];
        int rg0 = i0 + row0, rg1 = rg0 + 8;
#pragma unroll
        for (int nt = 0; nt < 8; nt++) {
            int col = h * 64 + (nt << 3) + c2;
            if (rg0 < LL)
                split_store2(g_cth, g_ctl, ((size_t)(b * LL + rg0)) * DD + col,
                             big[8 + nt][0] * li0, big[8 + nt][1] * li0);
            if (rg1 < LL)
                split_store2(g_cth, g_ctl, ((size_t)(b * LL + rg1)) * DD + col,
                             big[8 + nt][2] * li1, big[8 + nt][3] * li1);
        }
    }
}

// ---------------------------------------------------------------- launcher
extern "C" void kernel_launch(void* const* d_in, const int* in_sizes, int n_in,
                              void* d_out, int out_size)
{
    const float* x     = (const float*)d_in[0];
    const float* Wq    = (const float*)d_in[1];
    const float* bq    = (const float*)d_in[2];
    const float* Wk    = (const float*)d_in[3];
    const float* bk    = (const float*)d_in[4];
    const float* Wv    = (const float*)d_in[5];
    const float* bv    = (const float*)d_in[6];
    const float* Wo    = (const float*)d_in[7];
    const float* bo    = (const float*)d_in[8];
    const float* rel   = (const float*)d_in[9];
    const float* gamma = (const float*)d_in[10];
    const float* beta  = (const float*)d_in[11];
    float* out = (float*)d_out;

    __nv_bfloat16 *xnh, *xnl, *qh, *ql, *kh, *kl, *vh, *vl, *cth, *ctl, *wh, *wl, *relh, *rell;
    cudaGetSymbolAddress((void**)&xnh, g_xnh);
    cudaGetSymbolAddress((void**)&xnl, g_xnl);
    cudaGetSymbolAddress((void**)&qh,  g_qh);
    cudaGetSymbolAddress((void**)&ql,  g_ql);
    cudaGetSymbolAddress((void**)&kh,  g_kh);
    cudaGetSymbolAddress((void**)&kl,  g_kl);
    cudaGetSymbolAddress((void**)&vh,  g_vh);
    cudaGetSymbolAddress((void**)&vl,  g_vl);
    cudaGetSymbolAddress((void**)&cth, g_cth);
    cudaGetSymbolAddress((void**)&ctl, g_ctl);
    cudaGetSymbolAddress((void**)&wh,  g_wh);
    cudaGetSymbolAddress((void**)&wl,  g_wl);
    cudaGetSymbolAddress((void**)&relh, g_relh);
    cudaGetSymbolAddress((void**)&rell, g_rell);

    cudaFuncSetAttribute(attn_tc_kernel, cudaFuncAttributeMaxDynamicSharedMemorySize,
                         ATTN_SMEM);
    cudaFuncSetAttribute(gemm_tc_kernel, cudaFuncAttributeMaxDynamicSharedMemorySize,
                         GEMM_SMEM);

    // ln (s0) || weight/rel split (s2), then join — capture-safe (proven R9/R10)
    cudaStream_t s2;
    cudaStreamCreateWithFlags(&s2, cudaStreamNonBlocking);
    cudaEvent_t eFork, eWs;
    cudaEventCreateWithFlags(&eFork, cudaEventDisableTiming);
    cudaEventCreateWithFlags(&eWs,   cudaEventDisableTiming);
    cudaEventRecord(eFork, 0);
    cudaStreamWaitEvent(s2, eFork, 0);
    ln_kernel<<<NTOK, 128>>>(x, gamma, beta);
    split_all<<<1149, 256, 0, s2>>>(Wq, Wk, Wv, Wo, rel);
    cudaEventRecord(eWs, s2);
    cudaStreamWaitEvent(0, eWs, 0);

    // fused QKV
    dim3 gq(1536 / 128, (NTOK + 127) / 128);  // (12, 63)
    gemm_tc_kernel<<<gq, 256, GEMM_SMEM>>>(xnh, xnl, wh, wl, bq, bk, bv,
                                           nullptr, nullptr,
                                           qh, ql, kh, kl, vh, vl, 0);

    dim3 ga((LL + 63) / 64, BB * HH);  // (16, 64)
    attn_tc_kernel<<<ga, 256, ATTN_SMEM>>>(relh, rell);

    dim3 go(DD / 128, (NTOK + 127) / 128);    // (4, 63)
    gemm_tc_kernel<<<go, 256, GEMM_SMEM>>>(cth, ctl, wh + 3*DD*DD, wl + 3*DD*DD,
                                           bo, nullptr, nullptr,
                                           out, x,
                                           nullptr, nullptr, nullptr, nullptr,
                                           nullptr, nullptr, 1);
}